// round 3
// baseline (speedup 1.0000x reference)
#include <cuda_runtime.h>
#include <math.h>

#define HW      65536
#define OUT_C   128
#define NCH     256   // 2*OUT_C
#define EPSBN   1e-5f
#define NSTATB  64    // stats blocks

typedef unsigned long long u64;

// ---------------- packed f32x2 helpers (Blackwell FFMA2 path) -----------------
__device__ __forceinline__ u64 fma2(u64 a, u64 b, u64 c) {
    u64 d; asm("fma.rn.f32x2 %0, %1, %2, %3;" : "=l"(d) : "l"(a), "l"(b), "l"(c)); return d;
}
__device__ __forceinline__ u64 mul2(u64 a, u64 b) {
    u64 d; asm("mul.rn.f32x2 %0, %1, %2;" : "=l"(d) : "l"(a), "l"(b)); return d;
}
__device__ __forceinline__ u64 pk2(float lo, float hi) {
    u64 r; asm("mov.b64 %0, {%1, %2};" : "=l"(r) : "f"(lo), "f"(hi)); return r;
}
__device__ __forceinline__ void upk(u64 v, float& lo, float& hi) {
    asm("mov.b64 {%0, %1}, %2;" : "=f"(lo), "=f"(hi) : "l"(v));
}
#define NEG1_X2 0xBF800000BF800000ull   // (-1.0f, -1.0f)

// ---------------- per-channel packed constant block ---------------------------
struct __align__(16) ChP {
    u64 aAx, aAy, aAc, bAx, bAy, bAc;           // 6
    u64 Pr[4], Pi[4], Qr[4], Qi[4];             // 16
    u64 Rr[4], Ri[4], Tr[4], Ti[4];             // 16
    u64 Md[4];                                  // 4
    u64 MoX[6], MoY[6];                         // 12
    u64 pad[10];                                // -> 512B
};

__device__ ChP   g_chp[OUT_C];
__device__ float g_part[NSTATB * 5];

// ---------------- kernel 1: image moments (deterministic tree reduce) ----------
__global__ void stats_kernel(const float4* __restrict__ x4,
                             const float4* __restrict__ y4) {
    const int HW4 = HW / 4;
    float sx = 0.f, sy = 0.f, sxx = 0.f, syy = 0.f, sxy = 0.f;
    for (int p = blockIdx.x * blockDim.x + threadIdx.x; p < HW4;
         p += gridDim.x * blockDim.x) {
        float4 xv = __ldg(x4 + p), yv = __ldg(y4 + p);
        sx += xv.x + xv.y + xv.z + xv.w;
        sy += yv.x + yv.y + yv.z + yv.w;
        sxx = fmaf(xv.x, xv.x, fmaf(xv.y, xv.y, fmaf(xv.z, xv.z, fmaf(xv.w, xv.w, sxx))));
        syy = fmaf(yv.x, yv.x, fmaf(yv.y, yv.y, fmaf(yv.z, yv.z, fmaf(yv.w, yv.w, syy))));
        sxy = fmaf(xv.x, yv.x, fmaf(xv.y, yv.y, fmaf(xv.z, yv.z, fmaf(xv.w, yv.w, sxy))));
    }
    #pragma unroll
    for (int off = 16; off > 0; off >>= 1) {
        sx  += __shfl_down_sync(0xffffffffu, sx,  off);
        sy  += __shfl_down_sync(0xffffffffu, sy,  off);
        sxx += __shfl_down_sync(0xffffffffu, sxx, off);
        syy += __shfl_down_sync(0xffffffffu, syy, off);
        sxy += __shfl_down_sync(0xffffffffu, sxy, off);
    }
    __shared__ float sh[5][8];
    int w = threadIdx.x >> 5, l = threadIdx.x & 31;
    if (l == 0) { sh[0][w]=sx; sh[1][w]=sy; sh[2][w]=sxx; sh[3][w]=syy; sh[4][w]=sxy; }
    __syncthreads();
    if (threadIdx.x < 5) {
        float s = 0.f;
        #pragma unroll
        for (int i = 0; i < 8; ++i) s += sh[threadIdx.x][i];
        g_part[blockIdx.x * 5 + threadIdx.x] = s;
    }
}

// ---------------- kernel 2: per-channel circuit precompute --------------------
struct cpx { float r, i; };
__device__ __forceinline__ cpx cmul(cpx a, cpx b){ return {a.r*b.r - a.i*b.i, a.r*b.i + a.i*b.r}; }
__device__ __forceinline__ cpx cadd(cpx a, cpx b){ return {a.r + b.r, a.i + b.i}; }
__device__ __forceinline__ cpx csub(cpx a, cpx b){ return {a.r - b.r, a.i - b.i}; }
__device__ __forceinline__ cpx cconj(cpx a){ return {a.r, -a.i}; }

__device__ __forceinline__ u64 dupf(float v) {
    union { float2 f; u64 u; } t; t.f = make_float2(v, v); return t.u;
}

// psi <- CNOT * emb1(U(s,j,1)) * emb0(U(s,j,0)) * psi, for j = 0,1.
__device__ void build_layer(const float* qp, int s, int o, cpx A[4][4]) {
    for (int i = 0; i < 4; ++i)
        for (int j = 0; j < 4; ++j)
            A[i][j] = { (i == j) ? 1.f : 0.f, 0.f };
    for (int j = 0; j < 2; ++j) {
        for (int w = 0; w < 2; ++w) {
            const float* p = qp + (((s*2 + j) * NCH) + o*2 + w) * 3;
            float th = p[0], ph = p[1], lm = p[2];
            float st, ct; sincosf(0.5f * th, &st, &ct);
            float slm, clm; sincosf(lm, &slm, &clm);
            float sph, cph; sincosf(ph, &sph, &cph);
            float spl, cpl; sincosf(ph + lm, &spl, &cpl);
            cpx U00 = { ct, 0.f };
            cpx U01 = { -clm * st, -slm * st };
            cpx U10 = {  cph * st,  sph * st };
            cpx U11 = {  cpl * ct,  spl * ct };
            if (w == 0) { // wire 0: rows (q, 2+q)
                for (int q = 0; q < 2; ++q)
                    for (int c = 0; c < 4; ++c) {
                        cpx r0 = A[q][c], r1 = A[2+q][c];
                        A[q][c]   = cadd(cmul(U00, r0), cmul(U01, r1));
                        A[2+q][c] = cadd(cmul(U10, r0), cmul(U11, r1));
                    }
            } else {      // wire 1: rows (2q, 2q+1)
                for (int q = 0; q < 2; ++q)
                    for (int c = 0; c < 4; ++c) {
                        cpx r0 = A[2*q][c], r1 = A[2*q+1][c];
                        A[2*q][c]   = cadd(cmul(U00, r0), cmul(U01, r1));
                        A[2*q+1][c] = cadd(cmul(U10, r0), cmul(U11, r1));
                    }
            }
        }
        for (int c = 0; c < 4; ++c) { cpx t = A[2][c]; A[2][c] = A[3][c]; A[3][c] = t; }
    }
}

__global__ void precompute_kernel(const float* __restrict__ freq,
                                  const float* __restrict__ qp,
                                  const float* __restrict__ bnw,
                                  const float* __restrict__ bnb) {
    __shared__ float stats[5];
    if (threadIdx.x < 5) {
        double s = 0.0;
        for (int i = 0; i < NSTATB; ++i) s += (double)g_part[i*5 + threadIdx.x];
        stats[threadIdx.x] = (float)s;
    }
    __syncthreads();
    int o = threadIdx.x;
    if (o >= OUT_C) return;

    const float N  = (float)HW;
    float mx  = stats[0] / N, my = stats[1] / N;
    float Sxx = stats[2] / N - mx * mx;
    float Syy = stats[3] / N - my * my;
    float Sxy = stats[4] / N - mx * my;

    float gx[2], gy[2], gc[2];
    #pragma unroll
    for (int w = 0; w < 2; ++w) {
        int m = 2*o + w;
        float f0 = freq[m*2 + 0], f1 = freq[m*2 + 1];
        float mean = f0 * mx + f1 * my;
        float var  = f0*f0*Sxx + 2.f*f0*f1*Sxy + f1*f1*Syy;
        float s    = bnw[m] / sqrtf(var + EPSBN);
        gx[w] = f0 * s; gy[w] = f1 * s; gc[w] = bnb[m] - mean * s;
    }

    ChP cc;
    cc.aAx = dupf(0.5f*(gx[0]+gx[1])); cc.aAy = dupf(0.5f*(gy[0]+gy[1])); cc.aAc = dupf(0.5f*(gc[0]+gc[1]));
    cc.bAx = dupf(0.5f*(gx[0]-gx[1])); cc.bAy = dupf(0.5f*(gy[0]-gy[1])); cc.bAc = dupf(0.5f*(gc[0]-gc[1]));

    cpx A0[4][4], A1[4][4], A2[4][4];
    build_layer(qp, 0, o, A0);
    build_layer(qp, 1, o, A1);
    build_layer(qp, 2, o, A2);

    cpx v0[4];
    for (int j = 0; j < 4; ++j) v0[j] = A0[j][0];
    cpx C[4][4];
    for (int j = 0; j < 4; ++j)
        for (int k = 0; k < 4; ++k) C[j][k] = cmul(A1[j][k], v0[k]);

    // u = ca*P + sa*Q + cb*R + sb*T, with Q = i(C3-C0), T = i(C2-C1)
    for (int j = 0; j < 4; ++j) {
        cpx P  = cadd(C[j][0], C[j][3]);
        cpx dq = csub(C[j][3], C[j][0]);
        cpx R  = cadd(C[j][1], C[j][2]);
        cpx dt = csub(C[j][2], C[j][1]);
        cc.Pr[j] = dupf(P.r);   cc.Pi[j] = dupf(P.i);
        cc.Qr[j] = dupf(-dq.i); cc.Qi[j] = dupf(dq.r);
        cc.Rr[j] = dupf(R.r);   cc.Ri[j] = dupf(R.i);
        cc.Tr[j] = dupf(-dt.i); cc.Ti[j] = dupf(dt.r);
    }

    // M = A2^H (Z x I) A2
    cpx M[4][4];
    for (int j = 0; j < 4; ++j)
        for (int k = 0; k < 4; ++k) {
            cpx acc = {0.f, 0.f};
            for (int l = 0; l < 4; ++l) {
                float z = (l < 2) ? 1.f : -1.f;
                cpx t = cmul(cconj(A2[l][j]), A2[l][k]);
                acc.r += z * t.r; acc.i += z * t.i;
            }
            M[j][k] = acc;
        }
    for (int j = 0; j < 4; ++j) cc.Md[j] = dupf(M[j][j].r);
    int idx = 0;
    for (int j = 0; j < 4; ++j)
        for (int k = j+1; k < 4; ++k) {
            cc.MoX[idx] = dupf(2.f * M[j][k].r);
            cc.MoY[idx] = dupf(-2.f * M[j][k].i);
            idx++;
        }
    #pragma unroll
    for (int t = 0; t < 10; ++t) cc.pad[t] = 0ull;

    g_chp[o] = cc;
}

// ---------------- packed 2-pixel evaluation -----------------------------------
__device__ __forceinline__ u64 eval_pair(const ChP& cc, u64 x, u64 y) {
    u64 a = fma2(cc.aAx, x, fma2(cc.aAy, y, cc.aAc));
    u64 b = fma2(cc.bAx, x, fma2(cc.bAy, y, cc.bAc));
    float a0, a1, b0, b1;
    upk(a, a0, a1); upk(b, b0, b1);
    float sa0, ca0, sa1, ca1, sb0, cb0, sb1, cb1;
    __sincosf(a0, &sa0, &ca0); __sincosf(a1, &sa1, &ca1);
    __sincosf(b0, &sb0, &cb0); __sincosf(b1, &sb1, &cb1);
    u64 sa = pk2(sa0, sa1), ca = pk2(ca0, ca1);
    u64 sb = pk2(sb0, sb1), cb = pk2(cb0, cb1);
    u64 nsa = mul2(sa, NEG1_X2), nsb = mul2(sb, NEG1_X2);

    u64 ur[4], ui[4];
    #pragma unroll
    for (int j = 0; j < 4; ++j) {
        ur[j] = fma2(ca, cc.Pr[j], fma2(sa, cc.Qr[j], fma2(cb, cc.Rr[j], mul2(sb, cc.Tr[j]))));
        ui[j] = fma2(ca, cc.Pi[j], fma2(sa, cc.Qi[j], fma2(cb, cc.Ri[j], mul2(sb, cc.Ti[j]))));
    }

    // e = D*u, D = diag(e^{-ia}, e^{-ib}, e^{+ib}, e^{+ia})
    u64 er[4], ei[4];
    er[0] = fma2(ca, ur[0], mul2(sa,  ui[0]));  ei[0] = fma2(ca, ui[0], mul2(nsa, ur[0]));
    er[1] = fma2(cb, ur[1], mul2(sb,  ui[1]));  ei[1] = fma2(cb, ui[1], mul2(nsb, ur[1]));
    er[2] = fma2(cb, ur[2], mul2(nsb, ui[2]));  ei[2] = fma2(cb, ui[2], mul2(sb,  ur[2]));
    er[3] = fma2(ca, ur[3], mul2(nsa, ui[3]));  ei[3] = fma2(ca, ui[3], mul2(sa,  ur[3]));

    // ev = e^H M e   (|e_j| == |u_j| for diagonal terms)
    u64 ev = 0ull;
    #pragma unroll
    for (int j = 0; j < 4; ++j)
        ev = fma2(cc.Md[j], fma2(ur[j], ur[j], mul2(ui[j], ui[j])), ev);
    int idx = 0;
    #pragma unroll
    for (int j = 0; j < 4; ++j)
        #pragma unroll
        for (int k = j + 1; k < 4; ++k) {
            u64 tr = fma2(er[j], er[k], mul2(ei[j], ei[k]));
            u64 ti = fma2(er[j], ei[k], mul2(mul2(ei[j], er[k]), NEG1_X2));
            ev = fma2(cc.MoX[idx], tr, fma2(cc.MoY[idx], ti, ev));
            idx++;
        }
    return ev;
}

// ---------------- kernel 3: main, packed f32x2, 4 pixels/thread ----------------
__global__ void __launch_bounds__(256)
main_kernel(const ulonglong2* __restrict__ x2, const ulonglong2* __restrict__ y2,
            ulonglong2* __restrict__ out2) {
    const int o = blockIdx.y;
    const ChP& cc = g_chp[o];
    const int HWV = HW / 4;                 // ulonglong2 = 4 pixels
    ulonglong2* __restrict__ o0 = out2 + (size_t)o * HWV;

    for (int g = blockIdx.x * blockDim.x + threadIdx.x; g < HWV;
         g += gridDim.x * blockDim.x) {
        ulonglong2 X = __ldg(x2 + g);
        ulonglong2 Y = __ldg(y2 + g);
        ulonglong2 r;
        r.x = eval_pair(cc, X.x, Y.x);
        r.y = eval_pair(cc, X.y, Y.y);
        o0[g]                           = r;
        o0[g + (size_t)1 * OUT_C * HWV] = r;
        o0[g + (size_t)2 * OUT_C * HWV] = r;
        o0[g + (size_t)3 * OUT_C * HWV] = r;
    }
}

// ---------------- launch ------------------------------------------------------
extern "C" void kernel_launch(void* const* d_in, const int* in_sizes, int n_in,
                              void* d_out, int out_size) {
    const float* coords = (const float*)d_in[0];   // (4, 2, 256, 256)
    const float* freq   = (const float*)d_in[1];   // (256, 2)
    const float* qp     = (const float*)d_in[2];   // (1, 3, 2, 256, 3)
    const float* bnw    = (const float*)d_in[3];   // (256,)
    const float* bnb    = (const float*)d_in[4];   // (256,)

    stats_kernel<<<NSTATB, 256>>>((const float4*)coords,
                                  (const float4*)(coords + HW));
    precompute_kernel<<<1, 128>>>(freq, qp, bnw, bnb);

    dim3 grid(16, OUT_C);
    main_kernel<<<grid, 256>>>((const ulonglong2*)coords,
                               (const ulonglong2*)(coords + HW),
                               (ulonglong2*)d_out);
}

// round 4
// speedup vs baseline: 1.3736x; 1.3736x over previous
#include <cuda_runtime.h>
#include <math.h>

#define HW      65536
#define OUT_C   128
#define NCH     256   // 2*OUT_C
#define EPSBN   1e-5f
#define NSTATB  64    // stats blocks

// ---------------- per-channel constant pack (32 floats = 128B) ----------------
struct __align__(16) ChC {
    float g0x, g0y, g0c;   // alpha_n = g0x*x + g0y*y + g0c   (channel 2o)
    float g1x, g1y, g1c;   // beta_n
    float A00;
    float Ac[12];          // cos coeffs, canonical (p,q) order
    float As[12];          // sin coeffs
    float pad;
};

__device__ ChC   g_chc[OUT_C];
__device__ float g_part[NSTATB * 5];

// exact trig tables: ang16[t] = t * 22.5 deg ; ang8[s] = s * 45 deg
__constant__ float COS16[16] = {
    1.f, 0.92387953251128674f, 0.70710678118654752f, 0.38268343236508977f,
    0.f,-0.38268343236508977f,-0.70710678118654752f,-0.92387953251128674f,
   -1.f,-0.92387953251128674f,-0.70710678118654752f,-0.38268343236508977f,
    0.f, 0.38268343236508977f, 0.70710678118654752f, 0.92387953251128674f };
__constant__ float SIN16[16] = {
    0.f, 0.38268343236508977f, 0.70710678118654752f, 0.92387953251128674f,
    1.f, 0.92387953251128674f, 0.70710678118654752f, 0.38268343236508977f,
    0.f,-0.38268343236508977f,-0.70710678118654752f,-0.92387953251128674f,
   -1.f,-0.92387953251128674f,-0.70710678118654752f,-0.38268343236508977f };
__constant__ float COS8[8] = { 1.f, 0.70710678118654752f, 0.f,-0.70710678118654752f,
                              -1.f,-0.70710678118654752f, 0.f, 0.70710678118654752f };
__constant__ float SIN8[8] = { 0.f, 0.70710678118654752f, 1.f, 0.70710678118654752f,
                               0.f,-0.70710678118654752f,-1.f,-0.70710678118654752f };
// canonical (p,q) list, index 0..11
__constant__ int PL[12] = { 0, 0, 1, 1, 1, 1, 1, 2, 2, 2, 2, 2 };
__constant__ int QL[12] = { 1, 2,-2,-1, 0, 1, 2,-2,-1, 0, 1, 2 };

// ---------------- kernel 1: image moments (deterministic tree reduce) ----------
__global__ void stats_kernel(const float4* __restrict__ x4,
                             const float4* __restrict__ y4) {
    const int HW4 = HW / 4;
    float sx = 0.f, sy = 0.f, sxx = 0.f, syy = 0.f, sxy = 0.f;
    for (int p = blockIdx.x * blockDim.x + threadIdx.x; p < HW4;
         p += gridDim.x * blockDim.x) {
        float4 xv = __ldg(x4 + p), yv = __ldg(y4 + p);
        sx += xv.x + xv.y + xv.z + xv.w;
        sy += yv.x + yv.y + yv.z + yv.w;
        sxx = fmaf(xv.x, xv.x, fmaf(xv.y, xv.y, fmaf(xv.z, xv.z, fmaf(xv.w, xv.w, sxx))));
        syy = fmaf(yv.x, yv.x, fmaf(yv.y, yv.y, fmaf(yv.z, yv.z, fmaf(yv.w, yv.w, syy))));
        sxy = fmaf(xv.x, yv.x, fmaf(xv.y, yv.y, fmaf(xv.z, yv.z, fmaf(xv.w, yv.w, sxy))));
    }
    #pragma unroll
    for (int off = 16; off > 0; off >>= 1) {
        sx  += __shfl_down_sync(0xffffffffu, sx,  off);
        sy  += __shfl_down_sync(0xffffffffu, sy,  off);
        sxx += __shfl_down_sync(0xffffffffu, sxx, off);
        syy += __shfl_down_sync(0xffffffffu, syy, off);
        sxy += __shfl_down_sync(0xffffffffu, sxy, off);
    }
    __shared__ float sh[5][8];
    int w = threadIdx.x >> 5, l = threadIdx.x & 31;
    if (l == 0) { sh[0][w]=sx; sh[1][w]=sy; sh[2][w]=sxx; sh[3][w]=syy; sh[4][w]=sxy; }
    __syncthreads();
    if (threadIdx.x < 5) {
        float s = 0.f;
        #pragma unroll
        for (int i = 0; i < 8; ++i) s += sh[threadIdx.x][i];
        g_part[blockIdx.x * 5 + threadIdx.x] = s;
    }
}

// ---------------- kernel 2: BN fold (needs stats) -----------------------------
__global__ void bn_kernel(const float* __restrict__ freq,
                          const float* __restrict__ bnw,
                          const float* __restrict__ bnb) {
    __shared__ float stats[5];
    if (threadIdx.x < 5) {
        float s = 0.f;
        for (int i = 0; i < NSTATB; ++i) s += g_part[i*5 + threadIdx.x];
        stats[threadIdx.x] = s;
    }
    __syncthreads();
    int o = threadIdx.x;
    if (o >= OUT_C) return;
    const float N  = (float)HW;
    float mx  = stats[0] / N, my = stats[1] / N;
    float Sxx = stats[2] / N - mx * mx;
    float Syy = stats[3] / N - my * my;
    float Sxy = stats[4] / N - mx * my;
    float g[2][3];
    #pragma unroll
    for (int w = 0; w < 2; ++w) {
        int m = 2*o + w;
        float f0 = freq[m*2 + 0], f1 = freq[m*2 + 1];
        float mean = f0 * mx + f1 * my;
        float var  = f0*f0*Sxx + 2.f*f0*f1*Sxy + f1*f1*Syy;
        float s    = bnw[m] * rsqrtf(var + EPSBN);
        g[w][0] = f0 * s; g[w][1] = f1 * s; g[w][2] = bnb[m] - mean * s;
    }
    g_chc[o].g0x = g[0][0]; g_chc[o].g0y = g[0][1]; g_chc[o].g0c = g[0][2];
    g_chc[o].g1x = g[1][0]; g_chc[o].g1y = g[1][1]; g_chc[o].g1c = g[1][2];
}

// ---------------- kernel 3: circuit sampling + DFT projection -----------------
struct cpx { float r, i; };
__device__ __forceinline__ cpx cmul(cpx a, cpx b){ return {a.r*b.r - a.i*b.i, a.r*b.i + a.i*b.r}; }
__device__ __forceinline__ cpx cadd(cpx a, cpx b){ return {a.r + b.r, a.i + b.i}; }

// psi <- CNOT * emb1(U(s,j,1)) * emb0(U(s,j,0)) * psi, for j = 0,1.
__device__ void build_layer(const float* qp, int s, int o, cpx A[4][4]) {
    for (int i = 0; i < 4; ++i)
        for (int j = 0; j < 4; ++j)
            A[i][j] = { (i == j) ? 1.f : 0.f, 0.f };
    for (int j = 0; j < 2; ++j) {
        for (int w = 0; w < 2; ++w) {
            const float* p = qp + (((s*2 + j) * NCH) + o*2 + w) * 3;
            float th = p[0], ph = p[1], lm = p[2];
            float st, ct; sincosf(0.5f * th, &st, &ct);
            float slm, clm; sincosf(lm, &slm, &clm);
            float sph, cph; sincosf(ph, &sph, &cph);
            float spl, cpl; sincosf(ph + lm, &spl, &cpl);
            cpx U00 = { ct, 0.f };
            cpx U01 = { -clm * st, -slm * st };
            cpx U10 = {  cph * st,  sph * st };
            cpx U11 = {  cpl * ct,  spl * ct };
            if (w == 0) { // wire 0: rows (q, 2+q)
                for (int q = 0; q < 2; ++q)
                    for (int c = 0; c < 4; ++c) {
                        cpx r0 = A[q][c], r1 = A[2+q][c];
                        A[q][c]   = cadd(cmul(U00, r0), cmul(U01, r1));
                        A[2+q][c] = cadd(cmul(U10, r0), cmul(U11, r1));
                    }
            } else {      // wire 1: rows (2q, 2q+1)
                for (int q = 0; q < 2; ++q)
                    for (int c = 0; c < 4; ++c) {
                        cpx r0 = A[2*q][c], r1 = A[2*q+1][c];
                        A[2*q][c]   = cadd(cmul(U00, r0), cmul(U01, r1));
                        A[2*q+1][c] = cadd(cmul(U10, r0), cmul(U11, r1));
                    }
            }
        }
        for (int c = 0; c < 4; ++c) { cpx t = A[2][c]; A[2][c] = A[3][c]; A[3][c] = t; }
    }
}

// one block per channel; 64 threads = 8x8 sample grid; threads 0..12 project
__global__ void circuit_kernel(const float* __restrict__ qp) {
    const int o = blockIdx.x;
    const int t = threadIdx.x;
    __shared__ float sev[64];

    {   // every thread builds its own copies (redundant, cheap, parallel)
        cpx A0[4][4], A1[4][4], A2[4][4];
        build_layer(qp, 0, o, A0);
        build_layer(qp, 1, o, A1);
        build_layer(qp, 2, o, A2);
        cpx v0[4];
        #pragma unroll
        for (int j = 0; j < 4; ++j) v0[j] = A0[j][0];

        int k = t >> 3, l = t & 7;           // alpha = 2pi k/8, beta = 2pi l/8
        int ia = (k + l) & 15;               // a = pi(k+l)/8
        int ib = (k - l) & 15;               // b = pi(k-l)/8
        cpx ema = { COS16[ia], -SIN16[ia] }; // e^{-ia}
        cpx epa = { COS16[ia],  SIN16[ia] };
        cpx emb = { COS16[ib], -SIN16[ib] };
        cpx epb = { COS16[ib],  SIN16[ib] };

        cpx v[4];
        v[0] = cmul(ema, v0[0]); v[1] = cmul(emb, v0[1]);
        v[2] = cmul(epb, v0[2]); v[3] = cmul(epa, v0[3]);
        cpx u[4];
        #pragma unroll
        for (int j = 0; j < 4; ++j) {
            cpx acc = {0.f, 0.f};
            #pragma unroll
            for (int c = 0; c < 4; ++c) acc = cadd(acc, cmul(A1[j][c], v[c]));
            u[j] = acc;
        }
        cpx e[4];
        e[0] = cmul(ema, u[0]); e[1] = cmul(emb, u[1]);
        e[2] = cmul(epb, u[2]); e[3] = cmul(epa, u[3]);
        float ev = 0.f;
        #pragma unroll
        for (int j = 0; j < 4; ++j) {
            cpx acc = {0.f, 0.f};
            #pragma unroll
            for (int c = 0; c < 4; ++c) acc = cadd(acc, cmul(A2[j][c], e[c]));
            float m2 = acc.r * acc.r + acc.i * acc.i;
            ev += (j < 2) ? m2 : -m2;
        }
        sev[t] = ev;
    }
    __syncthreads();

    if (t == 12) {           // DC
        float s = 0.f;
        for (int i = 0; i < 64; ++i) s += sev[i];
        g_chc[o].A00 = s * (1.f / 64.f);
    } else if (t < 12) {     // harmonic t
        int p = PL[t], q = QL[t];
        float sc = 0.f, ss = 0.f;
        for (int k = 0; k < 8; ++k)
            for (int l = 0; l < 8; ++l) {
                int idx = (p * k + q * l) & 7;
                float e = sev[k * 8 + l];
                sc = fmaf(e, COS8[idx], sc);
                ss = fmaf(e, SIN8[idx], ss);
            }
        g_chc[o].Ac[t] = sc * (1.f / 32.f);
        g_chc[o].As[t] = ss * (1.f / 32.f);
    }
}

// ---------------- per-pixel evaluation (Fourier form) --------------------------
__device__ __forceinline__ float eval_point(const ChC& cc, float xv, float yv) {
    float al = fmaf(cc.g0x, xv, fmaf(cc.g0y, yv, cc.g0c));
    float be = fmaf(cc.g1x, xv, fmaf(cc.g1y, yv, cc.g1c));
    float s0, c0, s1, c1;
    __sincosf(al, &s0, &c0);
    __sincosf(be, &s1, &c1);

    // power ladder: z0 = e^{i al}, z1 = e^{i be}
    float pcc = c0*c1, pss = s0*s1, psc = s0*c1, pcs = c0*s1;
    float z11r = pcc - pss, z11i = psc + pcs;     // (1,1)
    float zm1r = pcc + pss, zm1i = psc - pcs;     // (1,-1)
    float z1sr = fmaf(c1, c1, -(s1*s1)), z1si = 2.f*c1*s1;   // (0,2)
    float z0sr = fmaf(c0, c0, -(s0*s0)), z0si = 2.f*c0*s0;   // (2,0)
    float z12r = fmaf(z11r, c1, -(z11i*s1)), z12i = fmaf(z11i, c1, z11r*s1);   // (1,2)
    float zm2r = fmaf(zm1r, c1,  zm1i*s1),   zm2i = fmaf(zm1i, c1, -(zm1r*s1)); // (1,-2)
    float z21r = fmaf(z11r, c0, -(z11i*s0)), z21i = fmaf(z11i, c0, z11r*s0);   // (2,1)
    float w1r  = fmaf(zm1r, c0, -(zm1i*s0)), w1i  = fmaf(zm1i, c0, zm1r*s0);   // (2,-1)
    float z22r = fmaf(z11r, z11r, -(z11i*z11i)), z22i = 2.f*z11r*z11i;         // (2,2)
    float w2r  = fmaf(zm1r, zm1r, -(zm1i*zm1i)), w2i  = 2.f*zm1r*zm1i;         // (2,-2)

    float ev = cc.A00;
    ev = fmaf(cc.Ac[0],  c1,   fmaf(cc.As[0],  s1,   ev));   // (0,1)
    ev = fmaf(cc.Ac[1],  z1sr, fmaf(cc.As[1],  z1si, ev));   // (0,2)
    ev = fmaf(cc.Ac[2],  zm2r, fmaf(cc.As[2],  zm2i, ev));   // (1,-2)
    ev = fmaf(cc.Ac[3],  zm1r, fmaf(cc.As[3],  zm1i, ev));   // (1,-1)
    ev = fmaf(cc.Ac[4],  c0,   fmaf(cc.As[4],  s0,   ev));   // (1,0)
    ev = fmaf(cc.Ac[5],  z11r, fmaf(cc.As[5],  z11i, ev));   // (1,1)
    ev = fmaf(cc.Ac[6],  z12r, fmaf(cc.As[6],  z12i, ev));   // (1,2)
    ev = fmaf(cc.Ac[7],  w2r,  fmaf(cc.As[7],  w2i,  ev));   // (2,-2)
    ev = fmaf(cc.Ac[8],  w1r,  fmaf(cc.As[8],  w1i,  ev));   // (2,-1)
    ev = fmaf(cc.Ac[9],  z0sr, fmaf(cc.As[9],  z0si, ev));   // (2,0)
    ev = fmaf(cc.Ac[10], z21r, fmaf(cc.As[10], z21i, ev));   // (2,1)
    ev = fmaf(cc.Ac[11], z22r, fmaf(cc.As[11], z22i, ev));   // (2,2)
    return ev;
}

// ---------------- kernel 4: main ----------------------------------------------
__global__ void __launch_bounds__(256)
main_kernel(const float4* __restrict__ x4, const float4* __restrict__ y4,
            float4* __restrict__ out4) {
    const int o = blockIdx.y;
    const ChC cc = g_chc[o];             // by-value -> registers
    const int HW4 = HW / 4;
    float4* __restrict__ o0 = out4 + (size_t)o * HW4;

    for (int g = blockIdx.x * blockDim.x + threadIdx.x; g < HW4;
         g += gridDim.x * blockDim.x) {
        float4 xv = __ldg(x4 + g);
        float4 yv = __ldg(y4 + g);
        float4 r;
        r.x = eval_point(cc, xv.x, yv.x);
        r.y = eval_point(cc, xv.y, yv.y);
        r.z = eval_point(cc, xv.z, yv.z);
        r.w = eval_point(cc, xv.w, yv.w);
        o0[g]                           = r;
        o0[g + (size_t)1 * OUT_C * HW4] = r;
        o0[g + (size_t)2 * OUT_C * HW4] = r;
        o0[g + (size_t)3 * OUT_C * HW4] = r;
    }
}

// ---------------- launch ------------------------------------------------------
extern "C" void kernel_launch(void* const* d_in, const int* in_sizes, int n_in,
                              void* d_out, int out_size) {
    const float* coords = (const float*)d_in[0];   // (4, 2, 256, 256)
    const float* freq   = (const float*)d_in[1];   // (256, 2)
    const float* qp     = (const float*)d_in[2];   // (1, 3, 2, 256, 3)
    const float* bnw    = (const float*)d_in[3];   // (256,)
    const float* bnb    = (const float*)d_in[4];   // (256,)

    stats_kernel<<<NSTATB, 256>>>((const float4*)coords,
                                  (const float4*)(coords + HW));
    circuit_kernel<<<OUT_C, 64>>>(qp);
    bn_kernel<<<1, 128>>>(freq, bnw, bnb);

    dim3 grid(16, OUT_C);
    main_kernel<<<grid, 256>>>((const float4*)coords,
                               (const float4*)(coords + HW),
                               (float4*)d_out);
}